// round 16
// baseline (speedup 1.0000x reference)
#include <cuda_runtime.h>
#include <cuda_bf16.h>
#include <math.h>
#include <stdint.h>

#define HID  2048
#define NSEQ 2048
#define NH   16
#define HD   128
#define TOPK 256

// ---------------- scratch (device globals; no allocation) ----------------
__device__ float g_xpart[16][HID];
__device__ float g_xbar[HID];
__device__ float g_qbarp[32][HID];
__device__ float g_qbar[HID];
__device__ float g_U[NH][HID];
__device__ float g_impp[8][NH * NSEQ];
__device__ float g_imp[NH * NSEQ];
__device__ int   g_idx[NH * TOPK];
__device__ int   g_cnt[NH];

__device__ __align__(16) __nv_bfloat16 g_Xh[NSEQ * HID];
__device__ __align__(16) __nv_bfloat16 g_Xl[NSEQ * HID];
__device__ __align__(16) __nv_bfloat16 g_Oh[NSEQ * HID];
__device__ __align__(16) __nv_bfloat16 g_Ol[NSEQ * HID];
__device__ __align__(16) __nv_bfloat16 g_Qh[NSEQ * HID];
__device__ __align__(16) __nv_bfloat16 g_Ql[NSEQ * HID];
__device__ __align__(16) __nv_bfloat16 g_Kselh[NH * TOPK * HD];
__device__ __align__(16) __nv_bfloat16 g_Ksell[NH * TOPK * HD];
__device__ __align__(16) __nv_bfloat16 g_Vselh[NH * TOPK * HD];
__device__ __align__(16) __nv_bfloat16 g_Vsell[NH * TOPK * HD];
__device__ __align__(16) __nv_bfloat16 g_Wh[4][HID * HID];   // W^T splits, [N][K]
__device__ __align__(16) __nv_bfloat16 g_Wl[4][HID * HID];

// ======================= PTX helpers (plain sm_103-safe) =======================
__device__ __forceinline__ void ldsm4(uint32_t addr, uint32_t* r) {
    asm volatile("ldmatrix.sync.aligned.m8n8.x4.shared.b16 {%0,%1,%2,%3}, [%4];"
                 : "=r"(r[0]), "=r"(r[1]), "=r"(r[2]), "=r"(r[3]) : "r"(addr));
}
__device__ __forceinline__ void ldsm4t(uint32_t addr, uint32_t* r) {
    asm volatile("ldmatrix.sync.aligned.m8n8.x4.trans.shared.b16 {%0,%1,%2,%3}, [%4];"
                 : "=r"(r[0]), "=r"(r[1]), "=r"(r[2]), "=r"(r[3]) : "r"(addr));
}
__device__ __forceinline__ void mma16816(float* d, const uint32_t* a, uint32_t b0, uint32_t b1) {
    asm volatile("mma.sync.aligned.m16n8k16.row.col.f32.bf16.bf16.f32 "
                 "{%0,%1,%2,%3}, {%4,%5,%6,%7}, {%8,%9}, {%0,%1,%2,%3};"
                 : "+f"(d[0]), "+f"(d[1]), "+f"(d[2]), "+f"(d[3])
                 : "r"(a[0]), "r"(a[1]), "r"(a[2]), "r"(a[3]), "r"(b0), "r"(b1));
}
#define CP16(dst, src) \
    asm volatile("cp.async.cg.shared.global [%0], [%1], 16;" :: "r"(dst), "l"(src))
#define CP_COMMIT() asm volatile("cp.async.commit_group;" ::: "memory")
#define CP_WAIT1()  asm volatile("cp.async.wait_group 1;" ::: "memory")
#define CP_WAIT0()  asm volatile("cp.async.wait_group 0;" ::: "memory")

__device__ __forceinline__ void split_pack(float2 v, uint32_t& hw, uint32_t& lw) {
    __nv_bfloat16 h0 = __float2bfloat16(v.x), h1 = __float2bfloat16(v.y);
    hw = (uint32_t)__bfloat16_as_ushort(h0) | ((uint32_t)__bfloat16_as_ushort(h1) << 16);
    __nv_bfloat16 l0 = __float2bfloat16(v.x - __bfloat162float(h0));
    __nv_bfloat16 l1 = __float2bfloat16(v.y - __bfloat162float(h1));
    lw = (uint32_t)__bfloat16_as_ushort(l0) | ((uint32_t)__bfloat16_as_ushort(l1) << 16);
}
__device__ __forceinline__ void split_store(__nv_bfloat16* Ch, __nv_bfloat16* Cl,
                                            int row, int col, float2 v) {
    uint32_t hw, lw;
    split_pack(v, hw, lw);
    *(uint32_t*)&Ch[(size_t)row * HID + col] = hw;
    *(uint32_t*)&Cl[(size_t)row * HID + col] = lw;
}
__device__ __forceinline__ void split_store128(__nv_bfloat16* Ch, __nv_bfloat16* Cl,
                                               int row, int col, float2 v) {
    uint32_t hw, lw;
    split_pack(v, hw, lw);
    *(uint32_t*)&Ch[(size_t)row * HD + col] = hw;
    *(uint32_t*)&Cl[(size_t)row * HD + col] = lw;
}

// ======================= split / transpose-split =======================
__global__ void split_f32(const float* __restrict__ x,
                          __nv_bfloat16* __restrict__ hi, __nv_bfloat16* __restrict__ lo) {
    int i = (blockIdx.x * 256 + threadIdx.x) * 4;
    float4 v = *(const float4*)(x + i);
    __nv_bfloat16 h0 = __float2bfloat16(v.x);
    __nv_bfloat16 h1 = __float2bfloat16(v.y);
    __nv_bfloat16 h2 = __float2bfloat16(v.z);
    __nv_bfloat16 h3 = __float2bfloat16(v.w);
    ushort4 hv = {__bfloat16_as_ushort(h0), __bfloat16_as_ushort(h1),
                  __bfloat16_as_ushort(h2), __bfloat16_as_ushort(h3)};
    __nv_bfloat16 l0 = __float2bfloat16(v.x - __bfloat162float(h0));
    __nv_bfloat16 l1 = __float2bfloat16(v.y - __bfloat162float(h1));
    __nv_bfloat16 l2 = __float2bfloat16(v.z - __bfloat162float(h2));
    __nv_bfloat16 l3 = __float2bfloat16(v.w - __bfloat162float(h3));
    ushort4 lv = {__bfloat16_as_ushort(l0), __bfloat16_as_ushort(l1),
                  __bfloat16_as_ushort(l2), __bfloat16_as_ushort(l3)};
    *(ushort4*)(hi + i) = hv;
    *(ushort4*)(lo + i) = lv;
}

// one weight: [K][N] fp32 -> [N][K] bf16 hi/lo at g_W{h,l}[widx]
__global__ void transpose_split1(const float* __restrict__ W, int widx) {
    __shared__ float t[32][33];
    __nv_bfloat16* Th = g_Wh[widx];
    __nv_bfloat16* Tl = g_Wl[widx];
    int n0 = blockIdx.x * 32, k0 = blockIdx.y * 32;
    int tx = threadIdx.x, ty = threadIdx.y;  // block (32, 8)
#pragma unroll
    for (int j = 0; j < 32; j += 8)
        t[ty + j][tx] = W[(size_t)(k0 + ty + j) * HID + n0 + tx];
    __syncthreads();
#pragma unroll
    for (int j = 0; j < 32; j += 8) {
        float v = t[tx][ty + j];
        __nv_bfloat16 h = __float2bfloat16(v);
        size_t o = (size_t)(n0 + ty + j) * HID + k0 + tx;
        Th[o] = h;
        Tl[o] = __float2bfloat16(v - __bfloat162float(h));
    }
}

// ======================= selection chain (side stream) =======================
__global__ void colsumx_part(const float* __restrict__ X) {
    int c = blockIdx.x * 256 + threadIdx.x;
    int n0 = blockIdx.y * 128;
    float s = 0.f;
#pragma unroll 8
    for (int n = 0; n < 128; ++n) s += X[(size_t)(n0 + n) * HID + c];
    g_xpart[blockIdx.y][c] = s;
}
__global__ void colsumx_final() {
    int c = blockIdx.x * 256 + threadIdx.x;
    float s = 0.f;
#pragma unroll
    for (int t = 0; t < 16; ++t) s += g_xpart[t][c];
    g_xbar[c] = s;
}

// qbar = xbar @ Wq + N*bq  (32-way split-K)
__global__ void qbar_part(const float* __restrict__ Wq) {
    int kc = blockIdx.x, jt = blockIdx.y, tid = threadIdx.x;
    int j = jt * 256 + tid;
    float acc = 0.f;
#pragma unroll 4
    for (int kk = 0; kk < 64; ++kk) {
        int k = kc * 64 + kk;
        acc += g_xbar[k] * Wq[(size_t)k * HID + j];
    }
    g_qbarp[kc][j] = acc;
}
__global__ void qbar_reduce(const float* __restrict__ bq) {
    int j = blockIdx.x * 256 + threadIdx.x;
    float s = 0.f;
#pragma unroll
    for (int c = 0; c < 32; ++c) s += g_qbarp[c][j];
    g_qbar[j] = s + (float)NSEQ * bq[j];
}

// U[h][k] = sum_d Wk[k, h*128+d] * qbar[h*128+d]   (one warp per k)
__global__ void u_kernel(const float* __restrict__ Wk) {
    if (blockIdx.x == 0 && threadIdx.x < NH) g_cnt[threadIdx.x] = 0;
    int warp = (blockIdx.x * 256 + threadIdx.x) >> 5;
    int lane = threadIdx.x & 31;
    int k = warp;
    const float* row = Wk + (size_t)k * HID;
#pragma unroll
    for (int h = 0; h < NH; ++h) {
        float4 w = *(const float4*)(row + h * 128 + lane * 4);
        float4 q = *(const float4*)(g_qbar + h * 128 + lane * 4);
        float s = w.x * q.x + w.y * q.y + w.z * q.z + w.w * q.w;
#pragma unroll
        for (int o = 16; o; o >>= 1) s += __shfl_xor_sync(0xffffffffu, s, o);
        if (!lane) g_U[h][k] = s;
    }
}

// imp = X @ U (split-K partials)
__global__ void imp_part(const float* __restrict__ X) {
    __shared__ float Us[16][256];
    int mt = blockIdx.x, kc = blockIdx.y, tid = threadIdx.x;
    for (int i = tid; i < 16 * 256; i += 256) {
        int h = i >> 8, kk = i & 255;
        Us[h][kk] = g_U[h][kc * 256 + kk];
    }
    __syncthreads();
    int m = mt * 128 + (tid >> 1);
    int hbase = (tid & 1) * 8;
    const float* xr = X + (size_t)m * HID + kc * 256;
    float acc[8] = {};
    for (int k = 0; k < 256; k += 4) {
        float4 x = *(const float4*)(xr + k);
#pragma unroll
        for (int hh = 0; hh < 8; ++hh) {
            int h = hbase + hh;
            acc[hh] += x.x * Us[h][k] + x.y * Us[h][k + 1]
                     + x.z * Us[h][k + 2] + x.w * Us[h][k + 3];
        }
    }
#pragma unroll
    for (int hh = 0; hh < 8; ++hh)
        g_impp[kc][(hbase + hh) * NSEQ + m] = acc[hh];
}
__global__ void imp_reduce() {
    int i = blockIdx.x * 256 + threadIdx.x;
    float s = 0.f;
#pragma unroll
    for (int c = 0; c < 8; ++c) s += g_impp[c][i];
    g_imp[i] = s;
}

// ---------------- top-k by rank counting (128 blocks: 8 segments/head) ----------------
__global__ void topk_kernel() {
    __shared__ float sv[NSEQ];
    int h = blockIdx.x >> 3, seg = blockIdx.x & 7, tid = threadIdx.x;
    for (int i = tid; i < NSEQ; i += 256) sv[i] = g_imp[h * NSEQ + i];
    __syncthreads();
    const float4* p4 = (const float4*)sv;
    int m = seg * 256 + tid;
    float v = sv[m];
    int rank = 0;
    for (int j4 = 0; j4 < NSEQ / 4; ++j4) {
        float4 x = p4[j4];
        int jb = j4 * 4;
        rank += (x.x > v) + (x.y > v) + (x.z > v) + (x.w > v);
        rank += (x.x == v && jb + 0 < m);
        rank += (x.y == v && jb + 1 < m);
        rank += (x.z == v && jb + 2 < m);
        rank += (x.w == v && jb + 3 < m);
    }
    if (rank < TOPK) {
        int pos = atomicAdd(&g_cnt[h], 1);
        g_idx[h * TOPK + pos] = m;
    }
}

// ======================= KV-sel gathered GEMM =======================
#define KV_STG  49152
#define KV_SMEM (2 * KV_STG + 256)

__global__ __launch_bounds__(256, 1)
void kvsel_gemm(const float* __restrict__ bk, const float* __restrict__ bv) {
    extern __shared__ char smem[];
    const uint32_t sb = (uint32_t)__cvta_generic_to_shared(smem);
    int* sidx = (int*)(smem + 2 * KV_STG);
    const int tid = threadIdx.x, lane = tid & 31, wid = tid >> 5;
    const int head = blockIdx.x >> 2;
    const int jbase = (blockIdx.x & 3) * 64;
    const __nv_bfloat16* Bh = g_Wh[1 + blockIdx.y] + (size_t)(head * 128) * HID;
    const __nv_bfloat16* Bl = g_Wl[1 + blockIdx.y] + (size_t)(head * 128) * HID;
    const float* bias = (blockIdx.y ? bv : bk) + head * 128;
    __nv_bfloat16* Ch = blockIdx.y ? g_Vselh : g_Kselh;
    __nv_bfloat16* Cl = blockIdx.y ? g_Vsell : g_Ksell;

    if (tid < 64) sidx[tid] = g_idx[head * 256 + jbase + tid];
    __syncthreads();

    const int wm = (wid >> 2) * 32, wn = (wid & 3) * 32;
    float d[8][4];
#pragma unroll
    for (int i = 0; i < 8; ++i) { d[i][0] = d[i][1] = d[i][2] = d[i][3] = 0.f; }

    const int grp = lane >> 3, lr = lane & 7;
    const int arow_b = wm + (grp & 1) * 8 + lr;
    const int brow_b = wn + (grp >> 1) * 8 + lr;
    const int akc_b = grp >> 1, bkc_b = grp & 1;

    auto load_stage = [&](int st, int k0) {
        uint32_t sbase = sb + st * KV_STG;
#pragma unroll
        for (int j = 0; j < 2; ++j) {
            int id = tid + j * 256;
            int r = id >> 3, c = id & 7;
            uint32_t doff = (uint32_t)(r * 128 + ((c ^ (r & 7)) << 4));
            size_t src = (size_t)sidx[r] * HID + k0 + c * 8;
            CP16(sbase + doff,        g_Xh + src);
            CP16(sbase + 8192 + doff, g_Xl + src);
        }
#pragma unroll
        for (int j = 0; j < 4; ++j) {
            int id = tid + j * 256;
            int r = id >> 3, c = id & 7;
            uint32_t doff = (uint32_t)(r * 128 + ((c ^ (r & 7)) << 4));
            size_t src = (size_t)r * HID + k0 + c * 8;
            CP16(sbase + 16384 + doff, Bh + src);
            CP16(sbase + 32768 + doff, Bl + src);
        }
        CP_COMMIT();
    };

    load_stage(0, 0);
    for (int kc = 0; kc < 32; ++kc) {
        if (kc + 1 < 32) {
            load_stage((kc + 1) & 1, (kc + 1) * 64);
            CP_WAIT1();
        } else {
            CP_WAIT0();
        }
        __syncthreads();
        const uint32_t base = sb + (kc & 1) * KV_STG;
        const uint32_t TAh = base, TAl = base + 8192;
        const uint32_t TBh = base + 16384, TBl = base + 32768;
#pragma unroll
        for (int ks = 0; ks < 4; ++ks) {
            const int akc8 = ks * 2 + akc_b;
            const int bkc8 = ks * 2 + bkc_b;
            uint32_t aH[2][4], bH[2][4];
#pragma unroll
            for (int f = 0; f < 2; ++f) {
                int row = arow_b + f * 16;
                ldsm4(TAh + (uint32_t)(row * 128 + ((akc8 ^ (row & 7)) << 4)), aH[f]);
            }
#pragma unroll
            for (int jn = 0; jn < 2; ++jn) {
                int row = brow_b + jn * 16;
                ldsm4(TBh + (uint32_t)(row * 128 + ((bkc8 ^ (row & 7)) << 4)), bH[jn]);
            }
#pragma unroll
            for (int f = 0; f < 2; ++f)
#pragma unroll
                for (int jn = 0; jn < 2; ++jn)
#pragma unroll
                    for (int sub = 0; sub < 2; ++sub)
                        mma16816(d[f * 4 + jn * 2 + sub], aH[f],
                                 bH[jn][sub * 2], bH[jn][sub * 2 + 1]);
            {
                uint32_t aL[2][4];
#pragma unroll
                for (int f = 0; f < 2; ++f) {
                    int row = arow_b + f * 16;
                    ldsm4(TAl + (uint32_t)(row * 128 + ((akc8 ^ (row & 7)) << 4)), aL[f]);
                }
#pragma unroll
                for (int f = 0; f < 2; ++f)
#pragma unroll
                    for (int jn = 0; jn < 2; ++jn)
#pragma unroll
                        for (int sub = 0; sub < 2; ++sub)
                            mma16816(d[f * 4 + jn * 2 + sub], aL[f],
                                     bH[jn][sub * 2], bH[jn][sub * 2 + 1]);
            }
            {
                uint32_t bL[2][4];
#pragma unroll
                for (int jn = 0; jn < 2; ++jn) {
                    int row = brow_b + jn * 16;
                    ldsm4(TBl + (uint32_t)(row * 128 + ((bkc8 ^ (row & 7)) << 4)), bL[jn]);
                }
#pragma unroll
                for (int f = 0; f < 2; ++f)
#pragma unroll
                    for (int jn = 0; jn < 2; ++jn)
#pragma unroll
                        for (int sub = 0; sub < 2; ++sub)
                            mma16816(d[f * 4 + jn * 2 + sub], aH[f],
                                     bL[jn][sub * 2], bL[jn][sub * 2 + 1]);
            }
        }
        __syncthreads();
    }

    const int rq = lane >> 2, cq = (lane & 3) * 2;
#pragma unroll
    for (int j = 0; j < 4; ++j) {
        int col = wn + j * 8 + cq;
        float2 bb = *(const float2*)&bias[col];
#pragma unroll
        for (int f = 0; f < 2; ++f) {
            const float* dd = d[f * 4 + j];
            int g = blockIdx.x * 64 + wm + f * 16 + rq;
            float2 o0 = {dd[0] + bb.x, dd[1] + bb.y};
            float2 o1 = {dd[2] + bb.x, dd[3] + bb.y};
            split_store128(Ch, Cl, g, col, o0);
            split_store128(Ch, Cl, g + 8, col, o1);
        }
    }
}

// ======================= HMMA bf16x3 GEMM (Q and O projections) =======================
#define OFF_AL 32768
#define OFF_BH 65536
#define OFF_BL 81920
#define GSTAGE 98304
#define GSMEM  (2 * GSTAGE)

__global__ __launch_bounds__(512, 1)
void gemm_bf16x3(const __nv_bfloat16* __restrict__ Ah, const __nv_bfloat16* __restrict__ Al,
                 const __nv_bfloat16* __restrict__ Bh, const __nv_bfloat16* __restrict__ Bl,
                 const float* __restrict__ bias, float* __restrict__ C,
                 __nv_bfloat16* __restrict__ Ch, __nv_bfloat16* __restrict__ Cl) {
    extern __shared__ char smem[];
    const uint32_t sb = (uint32_t)__cvta_generic_to_shared(smem);
    const int tid = threadIdx.x, lane = tid & 31, wid = tid >> 5;
    const int m0 = blockIdx.y * 256, n0 = blockIdx.x * 128;
    const int wm = (wid >> 2) * 64, wn = (wid & 3) * 32;

    const __nv_bfloat16* pAh = Ah + (size_t)m0 * HID;
    const __nv_bfloat16* pAl = Al + (size_t)m0 * HID;
    const __nv_bfloat16* pBh = Bh + (size_t)n0 * HID;
    const __nv_bfloat16* pBl = Bl + (size_t)n0 * HID;

    float d[16][4];
#pragma unroll
    for (int i = 0; i < 16; ++i) { d[i][0] = d[i][1] = d[i][2] = d[i][3] = 0.f; }

    const int grp = lane >> 3, lr = lane & 7;
    const int arow_b = wm + (grp & 1) * 8 + lr;
    const int brow_b = wn + (grp >> 1) * 8 + lr;
    const int akc_b = grp >> 1;
    const int bkc_b = grp & 1;

    auto load_stage = [&](int stage, int k0) {
        uint32_t sbase = sb + stage * GSTAGE;
#pragma unroll
        for (int j = 0; j < 4; ++j) {
            int id = tid + j * 512;
            int r = id >> 3, c = id & 7;
            uint32_t doff = (uint32_t)(r * 128 + ((c ^ (r & 7)) << 4));
            CP16(sbase + doff,          pAh + (size_t)r * HID + k0 + c * 8);
            CP16(sbase + OFF_AL + doff, pAl + (size_t)r * HID + k0 + c * 8);
        }
#pragma unroll
        for (int j = 0; j < 2; ++j) {
            int id = tid + j * 512;
            int r = id >> 3, c = id & 7;
            uint32_t doff = (uint32_t)(r * 128 + ((c ^ (r & 7)) << 4));
            CP16(sbase + OFF_BH + doff, pBh + (size_t)r * HID + k0 + c * 8);
            CP16(sbase + OFF_BL + doff, pBl + (size_t)r * HID + k0 + c * 8);
        }
        CP_COMMIT();
    };

    load_stage(0, 0);

    for (int kc = 0; kc < 32; ++kc) {
        if (kc + 1 < 32) {
            load_stage((kc + 1) & 1, (kc + 1) * 64);
            CP_WAIT1();
        } else {
            CP_WAIT0();
        }
        __syncthreads();

        const uint32_t base = sb + (kc & 1) * GSTAGE;
        const uint32_t TAh = base, TAl = base + OFF_AL;
        const uint32_t TBh = base + OFF_BH, TBl = base + OFF_BL;

#pragma unroll
        for (int ks = 0; ks < 4; ++ks) {
            const int akc8 = ks * 2 + akc_b;
            const int bkc8 = ks * 2 + bkc_b;
            uint32_t aH[4][4], bH[2][4];
#pragma unroll
            for (int f = 0; f < 4; ++f) {
                int row = arow_b + f * 16;
                ldsm4(TAh + (uint32_t)(row * 128 + ((akc8 ^ (row & 7)) << 4)), aH[f]);
            }
#pragma unroll
            for (int jn = 0; jn < 2; ++jn) {
                int row = brow_b + jn * 16;
                ldsm4(TBh + (uint32_t)(row * 128 + ((bkc8 ^ (row & 7)) << 4)), bH[jn]);
            }
#pragma unroll
            for (int f = 0; f < 4; ++f)
#pragma unroll
                for (int jn = 0; jn < 2; ++jn)
#pragma unroll
                    for (int sub = 0; sub < 2; ++sub)
                        mma16816(d[f * 4 + jn * 2 + sub], aH[f],
                                 bH[jn][sub * 2], bH[jn][sub * 2 + 1]);
            {
                uint32_t aL[4][4];
#pragma unroll
                for (int f = 0; f < 4; ++f) {
                    int row = arow_b + f * 16;
                    ldsm4(TAl + (uint32_t)(row * 128 + ((akc8 ^ (row & 7)) << 4)), aL[f]);
                }
#pragma unroll
                for (int f = 0; f < 4; ++f)
#pragma unroll
                    for (int jn = 0; jn < 2; ++jn)
#pragma unroll
                        for (int sub = 0; sub < 2; ++sub)
                            mma16816(d[f * 4 + jn * 2 + sub], aL[f],
                                     bH[jn][sub * 2], bH[jn][sub * 2 + 1]);
            }
            {
                uint32_t bL[2][4];
#pragma unroll
                for (int jn = 0; jn < 2; ++jn) {
                    int row = brow_b + jn * 16;
                    ldsm4(TBl + (uint32_t)(row * 128 + ((bkc8 ^ (row & 7)) << 4)), bL[jn]);
                }
#pragma unroll
                for (int f = 0; f < 4; ++f)
#pragma unroll
                    for (int jn = 0; jn < 2; ++jn)
#pragma unroll
                        for (int sub = 0; sub < 2; ++sub)
                            mma16816(d[f * 4 + jn * 2 + sub], aH[f],
                                     bL[jn][sub * 2], bL[jn][sub * 2 + 1]);
            }
        }
        __syncthreads();
    }

    const int rq = lane >> 2, cq = (lane & 3) * 2;
#pragma unroll
    for (int j = 0; j < 4; ++j) {
        int col = n0 + wn + j * 8 + cq;
        float2 bb = *(const float2*)&bias[col];
#pragma unroll
        for (int f = 0; f < 4; ++f) {
            const float* dd = d[f * 4 + j];
            int row = m0 + wm + f * 16 + rq;
            float2 o0 = {dd[0] + bb.x, dd[1] + bb.y};
            float2 o1 = {dd[2] + bb.x, dd[3] + bb.y};
            if (C) {
                *(float2*)&C[(size_t)row * HID + col]       = o0;
                *(float2*)&C[(size_t)(row + 8) * HID + col] = o1;
            }
            if (Ch) {
                split_store(Ch, Cl, row, col, o0);
                split_store(Ch, Cl, row + 8, col, o1);
            }
        }
    }
}

// ======================= HMMA bf16x3 sparse attention (dense Ksel/Vsel) =======================
#define AT_QH   0
#define AT_QL   16384
#define AT_KST  32768
#define AT_S    98304
#define ATTN_SMEM 163840

__device__ __forceinline__ void load_sel(uint32_t dstStage,
                                         const __nv_bfloat16* __restrict__ Hi,
                                         const __nv_bfloat16* __restrict__ Lo,
                                         int h, int kc, int tid) {
#pragma unroll
    for (int j = 0; j < 4; ++j) {
        int id = tid + j * 256;
        int r = id >> 4, c = id & 15;
        size_t g = (size_t)(h * TOPK + kc * 64 + r) * HD + c * 8;
        uint32_t dst = dstStage + (uint32_t)(r * 256 + ((c ^ (r & 7)) << 4));
        CP16(dst,         Hi + g);
        CP16(dst + 16384, Lo + g);
    }
}

__global__ __launch_bounds__(256, 1)
void attn_mma() {
    extern __shared__ char smc[];
    const uint32_t sb = (uint32_t)__cvta_generic_to_shared(smc);
    const int tid = threadIdx.x, lane = tid & 31, wid = tid >> 5;
    const int h = blockIdx.y, n0 = blockIdx.x * 64, HB = h * HD;
    const int grp = lane >> 3, lr = lane & 7;
    const int fm = wid >> 1;
    const int rq = lane >> 2, cq = (lane & 3) * 2;
    const float SCALE = 0.08838834764831845f;

#pragma unroll
    for (int j = 0; j < 4; ++j) {
        int id = tid + j * 256;
        int r = id >> 4, c = id & 15;
        uint32_t dst = sb + AT_QH + (uint32_t)(r * 256 + ((c ^ (r & 7)) << 4));
        CP16(dst,         g_Qh + (size_t)(n0 + r) * HID + HB + c * 8);
        CP16(dst + 16384, g_Ql + (size_t)(n0 + r) * HID + HB + c * 8);
    }
    load_sel(sb + AT_KST, g_Kselh, g_Ksell, h, 0, tid);
    CP_COMMIT();

    const int wn1 = (wid & 1) * 32;
    float* Sf = (float*)(smc + AT_S);
    for (int kc = 0; kc < 4; ++kc) {
        CP_WAIT0();
        __syncthreads();
        if (kc + 1 < 4) {
            load_sel(sb + AT_KST + ((kc + 1) & 1) * 32768, g_Kselh, g_Ksell, h, kc + 1, tid);
            CP_COMMIT();
        }
        const uint32_t KH = sb + AT_KST + (kc & 1) * 32768, KL = KH + 16384;
        const uint32_t QH = sb + AT_QH, QL = sb + AT_QL;
        float acc[4][4] = {};
        const int arow = fm * 16 + (grp & 1) * 8 + lr;
        const int brow = wn1 + (grp >> 1) * 8 + lr;
#pragma unroll
        for (int ks = 0; ks < 8; ++ks) {
            uint32_t aH[4], aL[4], bH[2][4], bL[2][4];
            {
                int ca = ks * 2 + (grp >> 1);
                uint32_t off = (uint32_t)(arow * 256 + ((ca ^ (arow & 7)) << 4));
                ldsm4(QH + off, aH);
                ldsm4(QL + off, aL);
            }
            {
                int cb = ks * 2 + (grp & 1);
#pragma unroll
                for (int hf = 0; hf < 2; ++hf) {
                    int row = brow + hf * 16;
                    uint32_t off = (uint32_t)(row * 256 + ((cb ^ (row & 7)) << 4));
                    ldsm4(KH + off, bH[hf]);
                    ldsm4(KL + off, bL[hf]);
                }
            }
#pragma unroll
            for (int hf = 0; hf < 2; ++hf)
#pragma unroll
                for (int sub = 0; sub < 2; ++sub)
                    mma16816(acc[hf * 2 + sub], aH, bH[hf][sub * 2], bH[hf][sub * 2 + 1]);
#pragma unroll
            for (int hf = 0; hf < 2; ++hf)
#pragma unroll
                for (int sub = 0; sub < 2; ++sub)
                    mma16816(acc[hf * 2 + sub], aH, bL[hf][sub * 2], bL[hf][sub * 2 + 1]);
#pragma unroll
            for (int hf = 0; hf < 2; ++hf)
#pragma unroll
                for (int sub = 0; sub < 2; ++sub)
                    mma16816(acc[hf * 2 + sub], aL, bH[hf][sub * 2], bH[hf][sub * 2 + 1]);
        }
#pragma unroll
        for (int jf = 0; jf < 4; ++jf) {
            int col = kc * 64 + wn1 + jf * 8 + cq;
            float2 v0 = {acc[jf][0] * SCALE, acc[jf][1] * SCALE};
            float2 v1 = {acc[jf][2] * SCALE, acc[jf][3] * SCALE};
            *(float2*)&Sf[(fm * 16 + rq) * 256 + col]     = v0;
            *(float2*)&Sf[(fm * 16 + rq + 8) * 256 + col] = v1;
        }
    }
    __syncthreads();

    load_sel(sb + AT_KST, g_Vselh, g_Vsell, h, 0, tid);
    CP_COMMIT();

    for (int r = wid; r < 64; r += 8) {
        float vals[8], mx = -1e30f;
        float* Sr = (float*)(smc + AT_S + r * 1024);
#pragma unroll
        for (int t = 0; t < 8; ++t) {
            vals[t] = Sr[lane + t * 32];
            mx = fmaxf(mx, vals[t]);
        }
#pragma unroll
        for (int o = 16; o; o >>= 1) mx = fmaxf(mx, __shfl_xor_sync(0xffffffffu, mx, o));
        float ssum = 0.f;
#pragma unroll
        for (int t = 0; t < 8; ++t) { vals[t] = expf(vals[t] - mx); ssum += vals[t]; }
#pragma unroll
        for (int o = 16; o; o >>= 1) ssum += __shfl_xor_sync(0xffffffffu, ssum, o);
        float inv = 1.0f / ssum;
        char* rowb = smc + AT_S + r * 1024;
#pragma unroll
        for (int t = 0; t < 8; ++t) {
            float w = vals[t] * inv;
            __nv_bfloat16 hi = __float2bfloat16(w);
            __nv_bfloat16 lo = __float2bfloat16(w - __bfloat162float(hi));
            int key = lane + t * 32;
            int c = key >> 3, wi = key & 7;
            int swz = ((c ^ (r & 7)) << 4) + wi * 2;
            *(__nv_bfloat16*)(rowb + swz)       = hi;
            *(__nv_bfloat16*)(rowb + 512 + swz) = lo;
        }
    }

    float oacc[8][4];
#pragma unroll
    for (int i = 0; i < 8; ++i) { oacc[i][0] = oacc[i][1] = oacc[i][2] = oacc[i][3] = 0.f; }
    const int wn3 = (wid & 1) * 64;
    for (int kc = 0; kc < 4; ++kc) {
        CP_WAIT0();
        __syncthreads();
        if (kc + 1 < 4) {
            load_sel(sb + AT_KST + ((kc + 1) & 1) * 32768, g_Vselh, g_Vsell, h, kc + 1, tid);
            CP_COMMIT();
        }
        const uint32_t VH = sb + AT_KST + (kc & 1) * 32768, VL = VH + 16384;
#pragma unroll
        for (int ks = 0; ks < 4; ++ks) {
            uint32_t aH[4], aL[4];
            {
                int cg = kc * 8 + ks * 2 + (grp >> 1);
                int arow = fm * 16 + (grp & 1) * 8 + lr;
                uint32_t off = (uint32_t)(arow * 1024 + ((cg ^ (arow & 7)) << 4));
                ldsm4(sb + AT_S + off, aH);
                ldsm4(sb + AT_S + off + 512, aL);
            }
            uint32_t bH[4][4], bL[4][4];
            {
                int vrow = ks * 16 + (grp & 1) * 8 + lr;
                uint32_t rbase = (uint32_t)(vrow * 256);
                int cbase = (wn3 >> 3) + (grp >> 1);
#pragma unroll
                for (int g4 = 0; g4 < 4; ++g4) {
                    int cn = cbase + g4 * 2;
                    uint32_t off = rbase + ((cn ^ (vrow & 7)) << 4);
                    ldsm4t(VH + off, bH[g4]);
                    ldsm4t(VL + off, bL[g4]);
                }
            }
#pragma unroll
            for (int g4 = 0; g4 < 4; ++g4)
#pragma unroll
                for (int s2 = 0; s2 < 2; ++s2)
                    mma16816(oacc[g4 * 2 + s2], aH, bH[g4][s2 * 2], bH[g4][s2 * 2 + 1]);
#pragma unroll
            for (int g4 = 0; g4 < 4; ++g4)
#pragma unroll
                for (int s2 = 0; s2 < 2; ++s2)
                    mma16816(oacc[g4 * 2 + s2], aH, bL[g4][s2 * 2], bL[g4][s2 * 2 + 1]);
#pragma unroll
            for (int g4 = 0; g4 < 4; ++g4)
#pragma unroll
                for (int s2 = 0; s2 < 2; ++s2)
                    mma16816(oacc[g4 * 2 + s2], aL, bH[g4][s2 * 2], bH[g4][s2 * 2 + 1]);
        }
    }

#pragma unroll
    for (int j = 0; j < 8; ++j) {
        int col = HB + wn3 + j * 8 + cq;
        int row = n0 + fm * 16 + rq;
        float2 v0 = {oacc[j][0], oacc[j][1]};
        float2 v1 = {oacc[j][2], oacc[j][3]};
        split_store(g_Oh, g_Ol, row, col, v0);
        split_store(g_Oh, g_Ol, row + 8, col, v1);
    }
}

// ======================= host =======================
extern "C" void kernel_launch(void* const* d_in, const int* in_sizes, int n_in,
                              void* d_out, int out_size) {
    const float* X  = (const float*)d_in[0];
    const float* Wq = (const float*)d_in[1];
    const float* bq = (const float*)d_in[2];
    const float* Wk = (const float*)d_in[3];
    const float* bk = (const float*)d_in[4];
    const float* Wv = (const float*)d_in[5];
    const float* bv = (const float*)d_in[6];
    const float* Wo = (const float*)d_in[7];
    const float* bo = (const float*)d_in[8];
    float* out = (float*)d_out;

    __nv_bfloat16 *Xh, *Xl, *Oh, *Ol, *Wh, *Wl, *Qh, *Ql;
    cudaGetSymbolAddress((void**)&Xh, g_Xh);
    cudaGetSymbolAddress((void**)&Xl, g_Xl);
    cudaGetSymbolAddress((void**)&Oh, g_Oh);
    cudaGetSymbolAddress((void**)&Ol, g_Ol);
    cudaGetSymbolAddress((void**)&Wh, g_Wh);
    cudaGetSymbolAddress((void**)&Wl, g_Wl);
    cudaGetSymbolAddress((void**)&Qh, g_Qh);
    cudaGetSymbolAddress((void**)&Ql, g_Ql);

    cudaFuncSetAttribute(gemm_bf16x3, cudaFuncAttributeMaxDynamicSharedMemorySize, GSMEM);
    cudaFuncSetAttribute(kvsel_gemm, cudaFuncAttributeMaxDynamicSharedMemorySize, KV_SMEM);
    cudaFuncSetAttribute(attn_mma, cudaFuncAttributeMaxDynamicSharedMemorySize, ATTN_SMEM);

    static cudaStream_t s1 = nullptr, s2 = nullptr;
    static cudaEvent_t ev0 = nullptr, evT = nullptr, evT2 = nullptr, evS = nullptr, evSel = nullptr;
    if (!s1) {
        cudaStreamCreateWithFlags(&s1, cudaStreamNonBlocking);
        cudaStreamCreateWithFlags(&s2, cudaStreamNonBlocking);
        cudaEventCreateWithFlags(&ev0, cudaEventDisableTiming);
        cudaEventCreateWithFlags(&evT, cudaEventDisableTiming);
        cudaEventCreateWithFlags(&evT2, cudaEventDisableTiming);
        cudaEventCreateWithFlags(&evS, cudaEventDisableTiming);
        cudaEventCreateWithFlags(&evSel, cudaEventDisableTiming);
    }

    const size_t WSZ = (size_t)HID * HID;
    dim3 gg(16, 8);   // Q/O GEMM: 128 CTAs single wave
    dim3 tgrid(64, 64);
    dim3 tblk(32, 8);

    cudaEventRecord(ev0, 0);
    cudaStreamWaitEvent(s1, ev0, 0);
    cudaStreamWaitEvent(s2, ev0, 0);

    // s1: Wq transpose first (Q GEMM dependency), then selection chain
    transpose_split1<<<tgrid, tblk, 0, s1>>>(Wq, 0);
    cudaEventRecord(evT, s1);                 // Wq^T ready
    colsumx_part<<<dim3(8, 16), 256, 0, s1>>>(X);
    colsumx_final<<<8, 256, 0, s1>>>();
    qbar_part<<<dim3(32, 8), 256, 0, s1>>>(Wq);
    qbar_reduce<<<8, 256, 0, s1>>>(bq);
    u_kernel<<<256, 256, 0, s1>>>(Wk);        // also zeroes g_cnt
    imp_part<<<dim3(16, 8), 256, 0, s1>>>(X);
    imp_reduce<<<128, 256, 0, s1>>>();
    topk_kernel<<<128, 256, 0, s1>>>();

    // s2: remaining weight transposes (Wk/Wv for kvsel, Wo for O GEMM)
    transpose_split1<<<tgrid, tblk, 0, s2>>>(Wk, 1);
    transpose_split1<<<tgrid, tblk, 0, s2>>>(Wv, 2);
    transpose_split1<<<tgrid, tblk, 0, s2>>>(Wo, 3);
    cudaEventRecord(evT2, s2);

    // main: X split
    split_f32<<<4096, 256>>>(X, Xh, Xl);
    cudaEventRecord(evS, 0);

    // s1: kvsel after topk + Xh/Xl + Wk/Wv transposes
    cudaStreamWaitEvent(s1, evS, 0);
    cudaStreamWaitEvent(s1, evT2, 0);
    kvsel_gemm<<<dim3(64, 2), 256, KV_SMEM, s1>>>(bk, bv);
    cudaEventRecord(evSel, s1);

    // main: Q GEMM (needs Wq^T + Xh/Xl)
    cudaStreamWaitEvent(0, evT, 0);
    gemm_bf16x3<<<gg, 512, GSMEM>>>(Xh, Xl, Wh + 0 * WSZ, Wl + 0 * WSZ, bq,
                                    nullptr, Qh, Ql);

    cudaStreamWaitEvent(0, evSel, 0);
    attn_mma<<<dim3(32, 16), 256, ATTN_SMEM>>>();

    gemm_bf16x3<<<gg, 512, GSMEM>>>(Oh, Ol, Wh + 3 * WSZ, Wl + 3 * WSZ, bo, out,
                                    nullptr, nullptr);
}

// round 17
// speedup vs baseline: 1.1065x; 1.1065x over previous
#include <cuda_runtime.h>
#include <cuda_bf16.h>
#include <math.h>
#include <stdint.h>

#define HID  2048
#define NSEQ 2048
#define NH   16
#define HD   128
#define TOPK 256

// ---------------- scratch (device globals; no allocation) ----------------
__device__ float g_xpart[16][HID];
__device__ float g_xbar[HID];
__device__ float g_qbarp[32][HID];
__device__ float g_qbar[HID];
__device__ float g_U[NH][HID];
__device__ float g_impp[8][NH * NSEQ];
__device__ float g_imp[NH * NSEQ];
__device__ int   g_idx[NH * TOPK];
__device__ int   g_cnt[NH];

__device__ __align__(16) __nv_bfloat16 g_Xh[NSEQ * HID];
__device__ __align__(16) __nv_bfloat16 g_Xl[NSEQ * HID];
__device__ __align__(16) __nv_bfloat16 g_Oh[NSEQ * HID];
__device__ __align__(16) __nv_bfloat16 g_Ol[NSEQ * HID];
__device__ __align__(16) __nv_bfloat16 g_Qh[NSEQ * HID];
__device__ __align__(16) __nv_bfloat16 g_Ql[NSEQ * HID];
__device__ __align__(16) __nv_bfloat16 g_Kselh[NH * TOPK * HD];
__device__ __align__(16) __nv_bfloat16 g_Ksell[NH * TOPK * HD];
__device__ __align__(16) __nv_bfloat16 g_Vselh[NH * TOPK * HD];
__device__ __align__(16) __nv_bfloat16 g_Vsell[NH * TOPK * HD];
__device__ __align__(16) __nv_bfloat16 g_Wh[4][HID * HID];   // W^T splits, [N][K]
__device__ __align__(16) __nv_bfloat16 g_Wl[4][HID * HID];

// ======================= PTX helpers (plain sm_103-safe) =======================
__device__ __forceinline__ void ldsm4(uint32_t addr, uint32_t* r) {
    asm volatile("ldmatrix.sync.aligned.m8n8.x4.shared.b16 {%0,%1,%2,%3}, [%4];"
                 : "=r"(r[0]), "=r"(r[1]), "=r"(r[2]), "=r"(r[3]) : "r"(addr));
}
__device__ __forceinline__ void ldsm4t(uint32_t addr, uint32_t* r) {
    asm volatile("ldmatrix.sync.aligned.m8n8.x4.trans.shared.b16 {%0,%1,%2,%3}, [%4];"
                 : "=r"(r[0]), "=r"(r[1]), "=r"(r[2]), "=r"(r[3]) : "r"(addr));
}
__device__ __forceinline__ void mma16816(float* d, const uint32_t* a, uint32_t b0, uint32_t b1) {
    asm volatile("mma.sync.aligned.m16n8k16.row.col.f32.bf16.bf16.f32 "
                 "{%0,%1,%2,%3}, {%4,%5,%6,%7}, {%8,%9}, {%0,%1,%2,%3};"
                 : "+f"(d[0]), "+f"(d[1]), "+f"(d[2]), "+f"(d[3])
                 : "r"(a[0]), "r"(a[1]), "r"(a[2]), "r"(a[3]), "r"(b0), "r"(b1));
}
#define CP16(dst, src) \
    asm volatile("cp.async.cg.shared.global [%0], [%1], 16;" :: "r"(dst), "l"(src))
#define CP_COMMIT() asm volatile("cp.async.commit_group;" ::: "memory")
#define CP_WAIT1()  asm volatile("cp.async.wait_group 1;" ::: "memory")
#define CP_WAIT0()  asm volatile("cp.async.wait_group 0;" ::: "memory")

__device__ __forceinline__ void split_pack(float2 v, uint32_t& hw, uint32_t& lw) {
    __nv_bfloat16 h0 = __float2bfloat16(v.x), h1 = __float2bfloat16(v.y);
    hw = (uint32_t)__bfloat16_as_ushort(h0) | ((uint32_t)__bfloat16_as_ushort(h1) << 16);
    __nv_bfloat16 l0 = __float2bfloat16(v.x - __bfloat162float(h0));
    __nv_bfloat16 l1 = __float2bfloat16(v.y - __bfloat162float(h1));
    lw = (uint32_t)__bfloat16_as_ushort(l0) | ((uint32_t)__bfloat16_as_ushort(l1) << 16);
}
__device__ __forceinline__ void split_store(__nv_bfloat16* Ch, __nv_bfloat16* Cl,
                                            int row, int col, float2 v) {
    uint32_t hw, lw;
    split_pack(v, hw, lw);
    *(uint32_t*)&Ch[(size_t)row * HID + col] = hw;
    *(uint32_t*)&Cl[(size_t)row * HID + col] = lw;
}
__device__ __forceinline__ void split_store128(__nv_bfloat16* Ch, __nv_bfloat16* Cl,
                                               int row, int col, float2 v) {
    uint32_t hw, lw;
    split_pack(v, hw, lw);
    *(uint32_t*)&Ch[(size_t)row * HD + col] = hw;
    *(uint32_t*)&Cl[(size_t)row * HD + col] = lw;
}

// ======================= split / transpose-split =======================
__global__ void split_f32(const float* __restrict__ x,
                          __nv_bfloat16* __restrict__ hi, __nv_bfloat16* __restrict__ lo) {
    int i = (blockIdx.x * 256 + threadIdx.x) * 4;
    float4 v = *(const float4*)(x + i);
    __nv_bfloat16 h0 = __float2bfloat16(v.x);
    __nv_bfloat16 h1 = __float2bfloat16(v.y);
    __nv_bfloat16 h2 = __float2bfloat16(v.z);
    __nv_bfloat16 h3 = __float2bfloat16(v.w);
    ushort4 hv = {__bfloat16_as_ushort(h0), __bfloat16_as_ushort(h1),
                  __bfloat16_as_ushort(h2), __bfloat16_as_ushort(h3)};
    __nv_bfloat16 l0 = __float2bfloat16(v.x - __bfloat162float(h0));
    __nv_bfloat16 l1 = __float2bfloat16(v.y - __bfloat162float(h1));
    __nv_bfloat16 l2 = __float2bfloat16(v.z - __bfloat162float(h2));
    __nv_bfloat16 l3 = __float2bfloat16(v.w - __bfloat162float(h3));
    ushort4 lv = {__bfloat16_as_ushort(l0), __bfloat16_as_ushort(l1),
                  __bfloat16_as_ushort(l2), __bfloat16_as_ushort(l3)};
    *(ushort4*)(hi + i) = hv;
    *(ushort4*)(lo + i) = lv;
}

// all 4 weights: [K][N] fp32 -> [N][K] bf16 hi/lo
__global__ void transpose_split4(const float* __restrict__ W0, const float* __restrict__ W1,
                                 const float* __restrict__ W2, const float* __restrict__ W3) {
    __shared__ float t[32][33];
    const float* W = blockIdx.z == 0 ? W0 : blockIdx.z == 1 ? W1 : blockIdx.z == 2 ? W2 : W3;
    __nv_bfloat16* Th = g_Wh[blockIdx.z];
    __nv_bfloat16* Tl = g_Wl[blockIdx.z];
    int n0 = blockIdx.x * 32, k0 = blockIdx.y * 32;
    int tx = threadIdx.x, ty = threadIdx.y;  // block (32, 8)
#pragma unroll
    for (int j = 0; j < 32; j += 8)
        t[ty + j][tx] = W[(size_t)(k0 + ty + j) * HID + n0 + tx];
    __syncthreads();
#pragma unroll
    for (int j = 0; j < 32; j += 8) {
        float v = t[tx][ty + j];
        __nv_bfloat16 h = __float2bfloat16(v);
        size_t o = (size_t)(n0 + ty + j) * HID + k0 + tx;
        Th[o] = h;
        Tl[o] = __float2bfloat16(v - __bfloat162float(h));
    }
}

// ======================= selection chain (side stream) =======================
__global__ void colsumx_part(const float* __restrict__ X) {
    int c = blockIdx.x * 256 + threadIdx.x;
    int n0 = blockIdx.y * 128;
    float s = 0.f;
#pragma unroll 8
    for (int n = 0; n < 128; ++n) s += X[(size_t)(n0 + n) * HID + c];
    g_xpart[blockIdx.y][c] = s;
}
__global__ void colsumx_final() {
    int c = blockIdx.x * 256 + threadIdx.x;
    float s = 0.f;
#pragma unroll
    for (int t = 0; t < 16; ++t) s += g_xpart[t][c];
    g_xbar[c] = s;
}

// qbar = xbar @ Wq + N*bq  (32-way split-K)
__global__ void qbar_part(const float* __restrict__ Wq) {
    int kc = blockIdx.x, jt = blockIdx.y, tid = threadIdx.x;
    int j = jt * 256 + tid;
    float acc = 0.f;
#pragma unroll 4
    for (int kk = 0; kk < 64; ++kk) {
        int k = kc * 64 + kk;
        acc += g_xbar[k] * Wq[(size_t)k * HID + j];
    }
    g_qbarp[kc][j] = acc;
}
__global__ void qbar_reduce(const float* __restrict__ bq) {
    int j = blockIdx.x * 256 + threadIdx.x;
    float s = 0.f;
#pragma unroll
    for (int c = 0; c < 32; ++c) s += g_qbarp[c][j];
    g_qbar[j] = s + (float)NSEQ * bq[j];
}

// U[h][k] = sum_d Wk[k, h*128+d] * qbar[h*128+d]   (one warp per k)
__global__ void u_kernel(const float* __restrict__ Wk) {
    if (blockIdx.x == 0 && threadIdx.x < NH) g_cnt[threadIdx.x] = 0;
    int warp = (blockIdx.x * 256 + threadIdx.x) >> 5;
    int lane = threadIdx.x & 31;
    int k = warp;
    const float* row = Wk + (size_t)k * HID;
#pragma unroll
    for (int h = 0; h < NH; ++h) {
        float4 w = *(const float4*)(row + h * 128 + lane * 4);
        float4 q = *(const float4*)(g_qbar + h * 128 + lane * 4);
        float s = w.x * q.x + w.y * q.y + w.z * q.z + w.w * q.w;
#pragma unroll
        for (int o = 16; o; o >>= 1) s += __shfl_xor_sync(0xffffffffu, s, o);
        if (!lane) g_U[h][k] = s;
    }
}

// imp = X @ U (split-K partials)
__global__ void imp_part(const float* __restrict__ X) {
    __shared__ float Us[16][256];
    int mt = blockIdx.x, kc = blockIdx.y, tid = threadIdx.x;
    for (int i = tid; i < 16 * 256; i += 256) {
        int h = i >> 8, kk = i & 255;
        Us[h][kk] = g_U[h][kc * 256 + kk];
    }
    __syncthreads();
    int m = mt * 128 + (tid >> 1);
    int hbase = (tid & 1) * 8;
    const float* xr = X + (size_t)m * HID + kc * 256;
    float acc[8] = {};
    for (int k = 0; k < 256; k += 4) {
        float4 x = *(const float4*)(xr + k);
#pragma unroll
        for (int hh = 0; hh < 8; ++hh) {
            int h = hbase + hh;
            acc[hh] += x.x * Us[h][k] + x.y * Us[h][k + 1]
                     + x.z * Us[h][k + 2] + x.w * Us[h][k + 3];
        }
    }
#pragma unroll
    for (int hh = 0; hh < 8; ++hh)
        g_impp[kc][(hbase + hh) * NSEQ + m] = acc[hh];
}
__global__ void imp_reduce() {
    int i = blockIdx.x * 256 + threadIdx.x;
    float s = 0.f;
#pragma unroll
    for (int c = 0; c < 8; ++c) s += g_impp[c][i];
    g_imp[i] = s;
}

// ---------------- top-k by rank counting (128 blocks: 8 segments/head) ----------------
__global__ void topk_kernel() {
    __shared__ float sv[NSEQ];
    int h = blockIdx.x >> 3, seg = blockIdx.x & 7, tid = threadIdx.x;
    for (int i = tid; i < NSEQ; i += 256) sv[i] = g_imp[h * NSEQ + i];
    __syncthreads();
    const float4* p4 = (const float4*)sv;
    int m = seg * 256 + tid;
    float v = sv[m];
    int rank = 0;
    for (int j4 = 0; j4 < NSEQ / 4; ++j4) {
        float4 x = p4[j4];
        int jb = j4 * 4;
        rank += (x.x > v) + (x.y > v) + (x.z > v) + (x.w > v);
        rank += (x.x == v && jb + 0 < m);
        rank += (x.y == v && jb + 1 < m);
        rank += (x.z == v && jb + 2 < m);
        rank += (x.w == v && jb + 3 < m);
    }
    if (rank < TOPK) {
        int pos = atomicAdd(&g_cnt[h], 1);
        g_idx[h * TOPK + pos] = m;
    }
}

// ======================= KV-sel gathered GEMM =======================
#define KV_STG  49152
#define KV_SMEM (2 * KV_STG + 256)

__global__ __launch_bounds__(256, 1)
void kvsel_gemm(const float* __restrict__ bk, const float* __restrict__ bv) {
    extern __shared__ char smem[];
    const uint32_t sb = (uint32_t)__cvta_generic_to_shared(smem);
    int* sidx = (int*)(smem + 2 * KV_STG);
    const int tid = threadIdx.x, lane = tid & 31, wid = tid >> 5;
    const int head = blockIdx.x >> 2;
    const int jbase = (blockIdx.x & 3) * 64;
    const __nv_bfloat16* Bh = g_Wh[1 + blockIdx.y] + (size_t)(head * 128) * HID;
    const __nv_bfloat16* Bl = g_Wl[1 + blockIdx.y] + (size_t)(head * 128) * HID;
    const float* bias = (blockIdx.y ? bv : bk) + head * 128;
    __nv_bfloat16* Ch = blockIdx.y ? g_Vselh : g_Kselh;
    __nv_bfloat16* Cl = blockIdx.y ? g_Vsell : g_Ksell;

    if (tid < 64) sidx[tid] = g_idx[head * 256 + jbase + tid];
    __syncthreads();

    const int wm = (wid >> 2) * 32, wn = (wid & 3) * 32;
    float d[8][4];
#pragma unroll
    for (int i = 0; i < 8; ++i) { d[i][0] = d[i][1] = d[i][2] = d[i][3] = 0.f; }

    const int grp = lane >> 3, lr = lane & 7;
    const int arow_b = wm + (grp & 1) * 8 + lr;
    const int brow_b = wn + (grp >> 1) * 8 + lr;
    const int akc_b = grp >> 1, bkc_b = grp & 1;

    auto load_stage = [&](int st, int k0) {
        uint32_t sbase = sb + st * KV_STG;
#pragma unroll
        for (int j = 0; j < 2; ++j) {
            int id = tid + j * 256;
            int r = id >> 3, c = id & 7;
            uint32_t doff = (uint32_t)(r * 128 + ((c ^ (r & 7)) << 4));
            size_t src = (size_t)sidx[r] * HID + k0 + c * 8;
            CP16(sbase + doff,        g_Xh + src);
            CP16(sbase + 8192 + doff, g_Xl + src);
        }
#pragma unroll
        for (int j = 0; j < 4; ++j) {
            int id = tid + j * 256;
            int r = id >> 3, c = id & 7;
            uint32_t doff = (uint32_t)(r * 128 + ((c ^ (r & 7)) << 4));
            size_t src = (size_t)r * HID + k0 + c * 8;
            CP16(sbase + 16384 + doff, Bh + src);
            CP16(sbase + 32768 + doff, Bl + src);
        }
        CP_COMMIT();
    };

    load_stage(0, 0);
    for (int kc = 0; kc < 32; ++kc) {
        if (kc + 1 < 32) {
            load_stage((kc + 1) & 1, (kc + 1) * 64);
            CP_WAIT1();
        } else {
            CP_WAIT0();
        }
        __syncthreads();
        const uint32_t base = sb + (kc & 1) * KV_STG;
        const uint32_t TAh = base, TAl = base + 8192;
        const uint32_t TBh = base + 16384, TBl = base + 32768;
#pragma unroll
        for (int ks = 0; ks < 4; ++ks) {
            const int akc8 = ks * 2 + akc_b;
            const int bkc8 = ks * 2 + bkc_b;
            uint32_t aH[2][4], bH[2][4];
#pragma unroll
            for (int f = 0; f < 2; ++f) {
                int row = arow_b + f * 16;
                ldsm4(TAh + (uint32_t)(row * 128 + ((akc8 ^ (row & 7)) << 4)), aH[f]);
            }
#pragma unroll
            for (int jn = 0; jn < 2; ++jn) {
                int row = brow_b + jn * 16;
                ldsm4(TBh + (uint32_t)(row * 128 + ((bkc8 ^ (row & 7)) << 4)), bH[jn]);
            }
#pragma unroll
            for (int f = 0; f < 2; ++f)
#pragma unroll
                for (int jn = 0; jn < 2; ++jn)
#pragma unroll
                    for (int sub = 0; sub < 2; ++sub)
                        mma16816(d[f * 4 + jn * 2 + sub], aH[f],
                                 bH[jn][sub * 2], bH[jn][sub * 2 + 1]);
            {
                uint32_t aL[2][4];
#pragma unroll
                for (int f = 0; f < 2; ++f) {
                    int row = arow_b + f * 16;
                    ldsm4(TAl + (uint32_t)(row * 128 + ((akc8 ^ (row & 7)) << 4)), aL[f]);
                }
#pragma unroll
                for (int f = 0; f < 2; ++f)
#pragma unroll
                    for (int jn = 0; jn < 2; ++jn)
#pragma unroll
                        for (int sub = 0; sub < 2; ++sub)
                            mma16816(d[f * 4 + jn * 2 + sub], aL[f],
                                     bH[jn][sub * 2], bH[jn][sub * 2 + 1]);
            }
            {
                uint32_t bL[2][4];
#pragma unroll
                for (int jn = 0; jn < 2; ++jn) {
                    int row = brow_b + jn * 16;
                    ldsm4(TBl + (uint32_t)(row * 128 + ((bkc8 ^ (row & 7)) << 4)), bL[jn]);
                }
#pragma unroll
                for (int f = 0; f < 2; ++f)
#pragma unroll
                    for (int jn = 0; jn < 2; ++jn)
#pragma unroll
                        for (int sub = 0; sub < 2; ++sub)
                            mma16816(d[f * 4 + jn * 2 + sub], aH[f],
                                     bL[jn][sub * 2], bL[jn][sub * 2 + 1]);
            }
        }
        __syncthreads();
    }

    const int rq = lane >> 2, cq = (lane & 3) * 2;
#pragma unroll
    for (int j = 0; j < 4; ++j) {
        int col = wn + j * 8 + cq;
        float2 bb = *(const float2*)&bias[col];
#pragma unroll
        for (int f = 0; f < 2; ++f) {
            const float* dd = d[f * 4 + j];
            int g = blockIdx.x * 64 + wm + f * 16 + rq;
            float2 o0 = {dd[0] + bb.x, dd[1] + bb.y};
            float2 o1 = {dd[2] + bb.x, dd[3] + bb.y};
            split_store128(Ch, Cl, g, col, o0);
            split_store128(Ch, Cl, g + 8, col, o1);
        }
    }
}

// ======================= HMMA bf16x3 GEMM (Q and O projections) =======================
#define OFF_AL 32768
#define OFF_BH 65536
#define OFF_BL 81920
#define GSTAGE 98304
#define GSMEM  (2 * GSTAGE)

__global__ __launch_bounds__(512, 1)
void gemm_bf16x3(const __nv_bfloat16* __restrict__ Ah, const __nv_bfloat16* __restrict__ Al,
                 const __nv_bfloat16* __restrict__ Bh, const __nv_bfloat16* __restrict__ Bl,
                 const float* __restrict__ bias, float* __restrict__ C,
                 __nv_bfloat16* __restrict__ Ch, __nv_bfloat16* __restrict__ Cl) {
    extern __shared__ char smem[];
    const uint32_t sb = (uint32_t)__cvta_generic_to_shared(smem);
    const int tid = threadIdx.x, lane = tid & 31, wid = tid >> 5;
    const int m0 = blockIdx.y * 256, n0 = blockIdx.x * 128;
    const int wm = (wid >> 2) * 64, wn = (wid & 3) * 32;

    const __nv_bfloat16* pAh = Ah + (size_t)m0 * HID;
    const __nv_bfloat16* pAl = Al + (size_t)m0 * HID;
    const __nv_bfloat16* pBh = Bh + (size_t)n0 * HID;
    const __nv_bfloat16* pBl = Bl + (size_t)n0 * HID;

    float d[16][4];
#pragma unroll
    for (int i = 0; i < 16; ++i) { d[i][0] = d[i][1] = d[i][2] = d[i][3] = 0.f; }

    const int grp = lane >> 3, lr = lane & 7;
    const int arow_b = wm + (grp & 1) * 8 + lr;
    const int brow_b = wn + (grp >> 1) * 8 + lr;
    const int akc_b = grp >> 1;
    const int bkc_b = grp & 1;

    auto load_stage = [&](int stage, int k0) {
        uint32_t sbase = sb + stage * GSTAGE;
#pragma unroll
        for (int j = 0; j < 4; ++j) {
            int id = tid + j * 512;
            int r = id >> 3, c = id & 7;
            uint32_t doff = (uint32_t)(r * 128 + ((c ^ (r & 7)) << 4));
            CP16(sbase + doff,          pAh + (size_t)r * HID + k0 + c * 8);
            CP16(sbase + OFF_AL + doff, pAl + (size_t)r * HID + k0 + c * 8);
        }
#pragma unroll
        for (int j = 0; j < 2; ++j) {
            int id = tid + j * 512;
            int r = id >> 3, c = id & 7;
            uint32_t doff = (uint32_t)(r * 128 + ((c ^ (r & 7)) << 4));
            CP16(sbase + OFF_BH + doff, pBh + (size_t)r * HID + k0 + c * 8);
            CP16(sbase + OFF_BL + doff, pBl + (size_t)r * HID + k0 + c * 8);
        }
        CP_COMMIT();
    };

    load_stage(0, 0);

    for (int kc = 0; kc < 32; ++kc) {
        if (kc + 1 < 32) {
            load_stage((kc + 1) & 1, (kc + 1) * 64);
            CP_WAIT1();
        } else {
            CP_WAIT0();
        }
        __syncthreads();

        const uint32_t base = sb + (kc & 1) * GSTAGE;
        const uint32_t TAh = base, TAl = base + OFF_AL;
        const uint32_t TBh = base + OFF_BH, TBl = base + OFF_BL;

#pragma unroll
        for (int ks = 0; ks < 4; ++ks) {
            const int akc8 = ks * 2 + akc_b;
            const int bkc8 = ks * 2 + bkc_b;
            uint32_t aH[4][4], bH[2][4];
#pragma unroll
            for (int f = 0; f < 4; ++f) {
                int row = arow_b + f * 16;
                ldsm4(TAh + (uint32_t)(row * 128 + ((akc8 ^ (row & 7)) << 4)), aH[f]);
            }
#pragma unroll
            for (int jn = 0; jn < 2; ++jn) {
                int row = brow_b + jn * 16;
                ldsm4(TBh + (uint32_t)(row * 128 + ((bkc8 ^ (row & 7)) << 4)), bH[jn]);
            }
#pragma unroll
            for (int f = 0; f < 4; ++f)
#pragma unroll
                for (int jn = 0; jn < 2; ++jn)
#pragma unroll
                    for (int sub = 0; sub < 2; ++sub)
                        mma16816(d[f * 4 + jn * 2 + sub], aH[f],
                                 bH[jn][sub * 2], bH[jn][sub * 2 + 1]);
            {
                uint32_t aL[4][4];
#pragma unroll
                for (int f = 0; f < 4; ++f) {
                    int row = arow_b + f * 16;
                    ldsm4(TAl + (uint32_t)(row * 128 + ((akc8 ^ (row & 7)) << 4)), aL[f]);
                }
#pragma unroll
                for (int f = 0; f < 4; ++f)
#pragma unroll
                    for (int jn = 0; jn < 2; ++jn)
#pragma unroll
                        for (int sub = 0; sub < 2; ++sub)
                            mma16816(d[f * 4 + jn * 2 + sub], aL[f],
                                     bH[jn][sub * 2], bH[jn][sub * 2 + 1]);
            }
            {
                uint32_t bL[2][4];
#pragma unroll
                for (int jn = 0; jn < 2; ++jn) {
                    int row = brow_b + jn * 16;
                    ldsm4(TBl + (uint32_t)(row * 128 + ((bkc8 ^ (row & 7)) << 4)), bL[jn]);
                }
#pragma unroll
                for (int f = 0; f < 4; ++f)
#pragma unroll
                    for (int jn = 0; jn < 2; ++jn)
#pragma unroll
                        for (int sub = 0; sub < 2; ++sub)
                            mma16816(d[f * 4 + jn * 2 + sub], aH[f],
                                     bL[jn][sub * 2], bL[jn][sub * 2 + 1]);
            }
        }
        __syncthreads();
    }

    const int rq = lane >> 2, cq = (lane & 3) * 2;
#pragma unroll
    for (int j = 0; j < 4; ++j) {
        int col = n0 + wn + j * 8 + cq;
        float2 bb = *(const float2*)&bias[col];
#pragma unroll
        for (int f = 0; f < 4; ++f) {
            const float* dd = d[f * 4 + j];
            int row = m0 + wm + f * 16 + rq;
            float2 o0 = {dd[0] + bb.x, dd[1] + bb.y};
            float2 o1 = {dd[2] + bb.x, dd[3] + bb.y};
            if (C) {
                *(float2*)&C[(size_t)row * HID + col]       = o0;
                *(float2*)&C[(size_t)(row + 8) * HID + col] = o1;
            }
            if (Ch) {
                split_store(Ch, Cl, row, col, o0);
                split_store(Ch, Cl, row + 8, col, o1);
            }
        }
    }
}

// ======================= HMMA bf16x3 sparse attention (dense Ksel/Vsel) =======================
#define AT_QH   0
#define AT_QL   16384
#define AT_KST  32768
#define AT_S    98304
#define ATTN_SMEM 163840

__device__ __forceinline__ void load_sel(uint32_t dstStage,
                                         const __nv_bfloat16* __restrict__ Hi,
                                         const __nv_bfloat16* __restrict__ Lo,
                                         int h, int kc, int tid) {
#pragma unroll
    for (int j = 0; j < 4; ++j) {
        int id = tid + j * 256;
        int r = id >> 4, c = id & 15;
        size_t g = (size_t)(h * TOPK + kc * 64 + r) * HD + c * 8;
        uint32_t dst = dstStage + (uint32_t)(r * 256 + ((c ^ (r & 7)) << 4));
        CP16(dst,         Hi + g);
        CP16(dst + 16384, Lo + g);
    }
}

__global__ __launch_bounds__(256, 1)
void attn_mma() {
    extern __shared__ char smc[];
    const uint32_t sb = (uint32_t)__cvta_generic_to_shared(smc);
    const int tid = threadIdx.x, lane = tid & 31, wid = tid >> 5;
    const int h = blockIdx.y, n0 = blockIdx.x * 64, HB = h * HD;
    const int grp = lane >> 3, lr = lane & 7;
    const int fm = wid >> 1;
    const int rq = lane >> 2, cq = (lane & 3) * 2;
    const float SCALE = 0.08838834764831845f;

#pragma unroll
    for (int j = 0; j < 4; ++j) {
        int id = tid + j * 256;
        int r = id >> 4, c = id & 15;
        uint32_t dst = sb + AT_QH + (uint32_t)(r * 256 + ((c ^ (r & 7)) << 4));
        CP16(dst,         g_Qh + (size_t)(n0 + r) * HID + HB + c * 8);
        CP16(dst + 16384, g_Ql + (size_t)(n0 + r) * HID + HB + c * 8);
    }
    load_sel(sb + AT_KST, g_Kselh, g_Ksell, h, 0, tid);
    CP_COMMIT();

    const int wn1 = (wid & 1) * 32;
    float* Sf = (float*)(smc + AT_S);
    for (int kc = 0; kc < 4; ++kc) {
        CP_WAIT0();
        __syncthreads();
        if (kc + 1 < 4) {
            load_sel(sb + AT_KST + ((kc + 1) & 1) * 32768, g_Kselh, g_Ksell, h, kc + 1, tid);
            CP_COMMIT();
        }
        const uint32_t KH = sb + AT_KST + (kc & 1) * 32768, KL = KH + 16384;
        const uint32_t QH = sb + AT_QH, QL = sb + AT_QL;
        float acc[4][4] = {};
        const int arow = fm * 16 + (grp & 1) * 8 + lr;
        const int brow = wn1 + (grp >> 1) * 8 + lr;
#pragma unroll
        for (int ks = 0; ks < 8; ++ks) {
            uint32_t aH[4], aL[4], bH[2][4], bL[2][4];
            {
                int ca = ks * 2 + (grp >> 1);
                uint32_t off = (uint32_t)(arow * 256 + ((ca ^ (arow & 7)) << 4));
                ldsm4(QH + off, aH);
                ldsm4(QL + off, aL);
            }
            {
                int cb = ks * 2 + (grp & 1);
#pragma unroll
                for (int hf = 0; hf < 2; ++hf) {
                    int row = brow + hf * 16;
                    uint32_t off = (uint32_t)(row * 256 + ((cb ^ (row & 7)) << 4));
                    ldsm4(KH + off, bH[hf]);
                    ldsm4(KL + off, bL[hf]);
                }
            }
#pragma unroll
            for (int hf = 0; hf < 2; ++hf)
#pragma unroll
                for (int sub = 0; sub < 2; ++sub)
                    mma16816(acc[hf * 2 + sub], aH, bH[hf][sub * 2], bH[hf][sub * 2 + 1]);
#pragma unroll
            for (int hf = 0; hf < 2; ++hf)
#pragma unroll
                for (int sub = 0; sub < 2; ++sub)
                    mma16816(acc[hf * 2 + sub], aH, bL[hf][sub * 2], bL[hf][sub * 2 + 1]);
#pragma unroll
            for (int hf = 0; hf < 2; ++hf)
#pragma unroll
                for (int sub = 0; sub < 2; ++sub)
                    mma16816(acc[hf * 2 + sub], aL, bH[hf][sub * 2], bH[hf][sub * 2 + 1]);
        }
#pragma unroll
        for (int jf = 0; jf < 4; ++jf) {
            int col = kc * 64 + wn1 + jf * 8 + cq;
            float2 v0 = {acc[jf][0] * SCALE, acc[jf][1] * SCALE};
            float2 v1 = {acc[jf][2] * SCALE, acc[jf][3] * SCALE};
            *(float2*)&Sf[(fm * 16 + rq) * 256 + col]     = v0;
            *(float2*)&Sf[(fm * 16 + rq + 8) * 256 + col] = v1;
        }
    }
    __syncthreads();

    load_sel(sb + AT_KST, g_Vselh, g_Vsell, h, 0, tid);
    CP_COMMIT();

    for (int r = wid; r < 64; r += 8) {
        float vals[8], mx = -1e30f;
        float* Sr = (float*)(smc + AT_S + r * 1024);
#pragma unroll
        for (int t = 0; t < 8; ++t) {
            vals[t] = Sr[lane + t * 32];
            mx = fmaxf(mx, vals[t]);
        }
#pragma unroll
        for (int o = 16; o; o >>= 1) mx = fmaxf(mx, __shfl_xor_sync(0xffffffffu, mx, o));
        float ssum = 0.f;
#pragma unroll
        for (int t = 0; t < 8; ++t) { vals[t] = expf(vals[t] - mx); ssum += vals[t]; }
#pragma unroll
        for (int o = 16; o; o >>= 1) ssum += __shfl_xor_sync(0xffffffffu, ssum, o);
        float inv = 1.0f / ssum;
        char* rowb = smc + AT_S + r * 1024;
#pragma unroll
        for (int t = 0; t < 8; ++t) {
            float w = vals[t] * inv;
            __nv_bfloat16 hi = __float2bfloat16(w);
            __nv_bfloat16 lo = __float2bfloat16(w - __bfloat162float(hi));
            int key = lane + t * 32;
            int c = key >> 3, wi = key & 7;
            int swz = ((c ^ (r & 7)) << 4) + wi * 2;
            *(__nv_bfloat16*)(rowb + swz)       = hi;
            *(__nv_bfloat16*)(rowb + 512 + swz) = lo;
        }
    }

    float oacc[8][4];
#pragma unroll
    for (int i = 0; i < 8; ++i) { oacc[i][0] = oacc[i][1] = oacc[i][2] = oacc[i][3] = 0.f; }
    const int wn3 = (wid & 1) * 64;
    for (int kc = 0; kc < 4; ++kc) {
        CP_WAIT0();
        __syncthreads();
        if (kc + 1 < 4) {
            load_sel(sb + AT_KST + ((kc + 1) & 1) * 32768, g_Vselh, g_Vsell, h, kc + 1, tid);
            CP_COMMIT();
        }
        const uint32_t VH = sb + AT_KST + (kc & 1) * 32768, VL = VH + 16384;
#pragma unroll
        for (int ks = 0; ks < 4; ++ks) {
            uint32_t aH[4], aL[4];
            {
                int cg = kc * 8 + ks * 2 + (grp >> 1);
                int arow = fm * 16 + (grp & 1) * 8 + lr;
                uint32_t off = (uint32_t)(arow * 1024 + ((cg ^ (arow & 7)) << 4));
                ldsm4(sb + AT_S + off, aH);
                ldsm4(sb + AT_S + off + 512, aL);
            }
            uint32_t bH[4][4], bL[4][4];
            {
                int vrow = ks * 16 + (grp & 1) * 8 + lr;
                uint32_t rbase = (uint32_t)(vrow * 256);
                int cbase = (wn3 >> 3) + (grp >> 1);
#pragma unroll
                for (int g4 = 0; g4 < 4; ++g4) {
                    int cn = cbase + g4 * 2;
                    uint32_t off = rbase + ((cn ^ (vrow & 7)) << 4);
                    ldsm4t(VH + off, bH[g4]);
                    ldsm4t(VL + off, bL[g4]);
                }
            }
#pragma unroll
            for (int g4 = 0; g4 < 4; ++g4)
#pragma unroll
                for (int s2 = 0; s2 < 2; ++s2)
                    mma16816(oacc[g4 * 2 + s2], aH, bH[g4][s2 * 2], bH[g4][s2 * 2 + 1]);
#pragma unroll
            for (int g4 = 0; g4 < 4; ++g4)
#pragma unroll
                for (int s2 = 0; s2 < 2; ++s2)
                    mma16816(oacc[g4 * 2 + s2], aH, bL[g4][s2 * 2], bL[g4][s2 * 2 + 1]);
#pragma unroll
            for (int g4 = 0; g4 < 4; ++g4)
#pragma unroll
                for (int s2 = 0; s2 < 2; ++s2)
                    mma16816(oacc[g4 * 2 + s2], aL, bH[g4][s2 * 2], bH[g4][s2 * 2 + 1]);
        }
    }

#pragma unroll
    for (int j = 0; j < 8; ++j) {
        int col = HB + wn3 + j * 8 + cq;
        int row = n0 + fm * 16 + rq;
        float2 v0 = {oacc[j][0], oacc[j][1]};
        float2 v1 = {oacc[j][2], oacc[j][3]};
        split_store(g_Oh, g_Ol, row, col, v0);
        split_store(g_Oh, g_Ol, row + 8, col, v1);
    }
}

// ======================= host =======================
extern "C" void kernel_launch(void* const* d_in, const int* in_sizes, int n_in,
                              void* d_out, int out_size) {
    const float* X  = (const float*)d_in[0];
    const float* Wq = (const float*)d_in[1];
    const float* bq = (const float*)d_in[2];
    const float* Wk = (const float*)d_in[3];
    const float* bk = (const float*)d_in[4];
    const float* Wv = (const float*)d_in[5];
    const float* bv = (const float*)d_in[6];
    const float* Wo = (const float*)d_in[7];
    const float* bo = (const float*)d_in[8];
    float* out = (float*)d_out;

    __nv_bfloat16 *Xh, *Xl, *Oh, *Ol, *Wh, *Wl, *Qh, *Ql;
    cudaGetSymbolAddress((void**)&Xh, g_Xh);
    cudaGetSymbolAddress((void**)&Xl, g_Xl);
    cudaGetSymbolAddress((void**)&Oh, g_Oh);
    cudaGetSymbolAddress((void**)&Ol, g_Ol);
    cudaGetSymbolAddress((void**)&Wh, g_Wh);
    cudaGetSymbolAddress((void**)&Wl, g_Wl);
    cudaGetSymbolAddress((void**)&Qh, g_Qh);
    cudaGetSymbolAddress((void**)&Ql, g_Ql);

    cudaFuncSetAttribute(gemm_bf16x3, cudaFuncAttributeMaxDynamicSharedMemorySize, GSMEM);
    cudaFuncSetAttribute(kvsel_gemm, cudaFuncAttributeMaxDynamicSharedMemorySize, KV_SMEM);
    cudaFuncSetAttribute(attn_mma, cudaFuncAttributeMaxDynamicSharedMemorySize, ATTN_SMEM);

    static cudaStream_t s1 = nullptr;
    static cudaEvent_t ev0 = nullptr, evT = nullptr, evS = nullptr, evSel = nullptr;
    if (!s1) {
        cudaStreamCreateWithFlags(&s1, cudaStreamNonBlocking);
        cudaEventCreateWithFlags(&ev0, cudaEventDisableTiming);
        cudaEventCreateWithFlags(&evT, cudaEventDisableTiming);
        cudaEventCreateWithFlags(&evS, cudaEventDisableTiming);
        cudaEventCreateWithFlags(&evSel, cudaEventDisableTiming);
    }

    const size_t WSZ = (size_t)HID * HID;
    dim3 gg(16, 8);   // Q/O GEMM: 128 CTAs single wave

    // fork: selection chain + transposes on s1; X split on main (R15 schedule)
    cudaEventRecord(ev0, 0);
    cudaStreamWaitEvent(s1, ev0, 0);

    transpose_split4<<<dim3(64, 64, 4), dim3(32, 8), 0, s1>>>(Wq, Wk, Wv, Wo);
    cudaEventRecord(evT, s1);                // transposes done (Q GEMM needs Wq^T)
    colsumx_part<<<dim3(8, 16), 256, 0, s1>>>(X);
    colsumx_final<<<8, 256, 0, s1>>>();
    qbar_part<<<dim3(32, 8), 256, 0, s1>>>(Wq);
    qbar_reduce<<<8, 256, 0, s1>>>(bq);
    u_kernel<<<256, 256, 0, s1>>>(Wk);       // also zeroes g_cnt
    imp_part<<<dim3(16, 8), 256, 0, s1>>>(X);
    imp_reduce<<<128, 256, 0, s1>>>();
    topk_kernel<<<128, 256, 0, s1>>>();

    split_f32<<<4096, 256>>>(X, Xh, Xl);
    cudaEventRecord(evS, 0);                 // Xh/Xl ready (kvsel gathers from them)
    cudaStreamWaitEvent(s1, evS, 0);
    kvsel_gemm<<<dim3(64, 2), 256, KV_SMEM, s1>>>(bk, bv);
    cudaEventRecord(evSel, s1);

    cudaStreamWaitEvent(0, evT, 0);
    gemm_bf16x3<<<gg, 512, GSMEM>>>(Xh, Xl, Wh + 0 * WSZ, Wl + 0 * WSZ, bq,
                                    nullptr, Qh, Ql);

    cudaStreamWaitEvent(0, evSel, 0);
    attn_mma<<<dim3(32, 16), 256, ATTN_SMEM>>>();

    gemm_bf16x3<<<gg, 512, GSMEM>>>(Oh, Ol, Wh + 3 * WSZ, Wl + 3 * WSZ, bo, out,
                                    nullptr, nullptr);
}